// round 10
// baseline (speedup 1.0000x reference)
#include <cuda_runtime.h>
#include <cstdint>

// Problem constants
#define B_   4
#define L_   2048
#define D_   1024
#define H_   16
#define HD_  64
#define MTOT (B_ * L_)   // 8192

#define QSCALE 0.18033688011112042f   // 0.125 * log2(e)

// Scratch (device globals; no allocation allowed)
__device__ float g_Q[MTOT * D_];
__device__ float g_K[MTOT * D_];
__device__ float g_V[MTOT * D_];
__device__ float g_X[MTOT * D_];
// Pre-rounded (tf32) operand copies
__device__ float g_QI[MTOT * D_];
__device__ float g_KI[MTOT * D_];
__device__ float g_VI[MTOT * D_];
__device__ float g_Wq[D_ * D_];
__device__ float g_Wk[D_ * D_];
__device__ float g_Wv[D_ * D_];
__device__ float g_Wo[D_ * D_];

// ===========================================================================
// Helpers
// ===========================================================================
__device__ __forceinline__ float to_tf32(float x) {
    float y;
    asm("cvt.rna.tf32.f32 %0, %1;" : "=f"(y) : "f"(x));
    return y;
}

__device__ __forceinline__ float ex2_(float x) {
    float y;
    asm("ex2.approx.ftz.f32 %0, %1;" : "=f"(y) : "f"(x));
    return y;
}

__device__ __forceinline__ void mma_tf32_16x8x8(
    float* d, const uint32_t* a, const uint32_t* b)
{
    asm volatile(
        "mma.sync.aligned.m16n8k8.row.col.f32.tf32.tf32.f32 "
        "{%0,%1,%2,%3}, {%4,%5,%6,%7}, {%8,%9}, {%0,%1,%2,%3};"
        : "+f"(d[0]), "+f"(d[1]), "+f"(d[2]), "+f"(d[3])
        : "r"(a[0]), "r"(a[1]), "r"(a[2]), "r"(a[3]),
          "r"(b[0]), "r"(b[1]));
}

__device__ __forceinline__ uint32_t smem_u32(const void* p) {
    uint32_t a;
    asm("{ .reg .u64 t; cvta.to.shared.u64 t, %1; cvt.u32.u64 %0, t; }"
        : "=r"(a) : "l"(p));
    return a;
}

#define CPASYNC16(dst_u32, src) \
    asm volatile("cp.async.cg.shared.global [%0], [%1], 16;" \
        :: "r"(dst_u32), "l"(src))
#define CPASYNC_COMMIT() asm volatile("cp.async.commit_group;" ::: "memory")
#define CPASYNC_WAIT1()  asm volatile("cp.async.wait_group 1;" ::: "memory")

// ===========================================================================
// Pre-round pass: tf32-round inputs and weights into scratch.
// ===========================================================================
__global__ __launch_bounds__(256) void preround_kernel(
    const float* __restrict__ q, const float* __restrict__ k,
    const float* __restrict__ v,
    const float* __restrict__ wq, const float* __restrict__ wk,
    const float* __restrict__ wv, const float* __restrict__ wo)
{
    const int z = blockIdx.y;
    const float* s; float* d; int n;
    switch (z) {
        case 0: s = q;  d = g_QI; n = MTOT * D_; break;
        case 1: s = k;  d = g_KI; n = MTOT * D_; break;
        case 2: s = v;  d = g_VI; n = MTOT * D_; break;
        case 3: s = wq; d = g_Wq; n = D_ * D_;   break;
        case 4: s = wk; d = g_Wk; n = D_ * D_;   break;
        case 5: s = wv; d = g_Wv; n = D_ * D_;   break;
        default: s = wo; d = g_Wo; n = D_ * D_;  break;
    }
    const int idx = (blockIdx.x * 256 + threadIdx.x) * 4;
    if (idx < n) {
        float4 x = *reinterpret_cast<const float4*>(s + idx);
        x.x = to_tf32(x.x); x.y = to_tf32(x.y);
        x.z = to_tf32(x.z); x.w = to_tf32(x.w);
        *reinterpret_cast<float4*>(d + idx) = x;
    }
}

// ===========================================================================
// GEMM: Y[M,N] = X[M,K] @ W[N,K]^T + bias[N]
// CTA tile 128x256, warp tile 64x64 (8 warps, 2x4). BK=32, 3-stage cp.async.
// Operands pre-rounded tf32. 1 CTA/SM (smem 162KB).
// MODE 0: fp32 out. MODE 1: out = tf32_round((acc+bias)*scale)
// ===========================================================================
#define GBK 32
#define NCH (D_ / GBK)          // 32
#define LDW 36                  // padded row stride (words)
#define A_TW (128 * LDW)        // 4608 words
#define B_TW (256 * LDW)        // 9216 words
#define STG_W (A_TW + B_TW)     // 13824 words per stage
#define GEMM_SMEM_BYTES (3 * STG_W * 4)   // 165888

template <int MODE>
__device__ __forceinline__ void gemm_body(
    const float* __restrict__ X, const float* __restrict__ W,
    const float* __restrict__ bias, float* __restrict__ Y,
    float scale, int bx, int by, float* sm)
{
    const int t    = threadIdx.x;
    const int lane = t & 31;
    const int wid  = t >> 5;
    const int wm   = (wid & 1) * 64;
    const int wn   = (wid >> 1) * 64;

    const float* Ag = X + (size_t)by * 128 * D_;
    const float* Bg = W + (size_t)bx * 256 * D_;

    const uint32_t sbase = smem_u32(sm);

    float acc[4][8][4];
#pragma unroll
    for (int mf = 0; mf < 4; mf++)
#pragma unroll
        for (int nf = 0; nf < 8; nf++)
#pragma unroll
            for (int r = 0; r < 4; r++) acc[mf][nf][r] = 0.f;

#define FILLG(k0, stg)                                                        \
    do {                                                                      \
        const uint32_t ab_ = sbase + (uint32_t)(stg) * (STG_W * 4);           \
        const uint32_t bb_ = ab_ + A_TW * 4;                                  \
        _Pragma("unroll")                                                     \
        for (int j = 0; j < 4; j++) {                                         \
            const int i_ = t + j * 256;                                       \
            const int r_ = i_ >> 3;                                           \
            const int c_ = (i_ & 7) * 4;                                      \
            CPASYNC16(ab_ + (uint32_t)(r_ * LDW + c_) * 4,                    \
                      Ag + (size_t)r_ * D_ + (k0) + c_);                      \
        }                                                                     \
        _Pragma("unroll")                                                     \
        for (int j = 0; j < 8; j++) {                                         \
            const int i_ = t + j * 256;                                       \
            const int r_ = i_ >> 3;                                           \
            const int c_ = (i_ & 7) * 4;                                      \
            CPASYNC16(bb_ + (uint32_t)(r_ * LDW + c_) * 4,                    \
                      Bg + (size_t)r_ * D_ + (k0) + c_);                      \
        }                                                                     \
    } while (0)

    FILLG(0, 0);   CPASYNC_COMMIT();
    FILLG(GBK, 1); CPASYNC_COMMIT();

    const int qr = lane >> 2;
    const int qc = lane & 3;

    int stg = 0;
    for (int c = 0; c < NCH; c++) {
        CPASYNC_WAIT1();
        __syncthreads();

        const uint32_t* Au = reinterpret_cast<const uint32_t*>(sm + stg * STG_W);
        const uint32_t* Bu = Au + A_TW;

#pragma unroll
        for (int ks = 0; ks < GBK / 8; ks++) {
            const int kb = ks * 8;
            uint32_t afr[4][4], bfr[8][2];
#pragma unroll
            for (int mf = 0; mf < 4; mf++) {
                const int r0 = wm + mf * 16 + qr;
                afr[mf][0] = Au[r0 * LDW + kb + qc];
                afr[mf][1] = Au[(r0 + 8) * LDW + kb + qc];
                afr[mf][2] = Au[r0 * LDW + kb + 4 + qc];
                afr[mf][3] = Au[(r0 + 8) * LDW + kb + 4 + qc];
            }
#pragma unroll
            for (int nf = 0; nf < 8; nf++) {
                const int n0 = wn + nf * 8 + qr;
                bfr[nf][0] = Bu[n0 * LDW + kb + qc];
                bfr[nf][1] = Bu[n0 * LDW + kb + 4 + qc];
            }
#pragma unroll
            for (int mf = 0; mf < 4; mf++)
#pragma unroll
                for (int nf = 0; nf < 8; nf++)
                    mma_tf32_16x8x8(acc[mf][nf], afr[mf], bfr[nf]);
        }

        const int cn = c + 2;
        if (cn < NCH) {
            const int ns = (stg + 2 > 2) ? stg - 1 : stg + 2;
            FILLG(cn * GBK, ns);
        }
        CPASYNC_COMMIT();
        stg = (stg + 1 > 2) ? 0 : stg + 1;
    }

    const int gm = by * 128 + wm;
    const int gn = bx * 256 + wn;
#pragma unroll
    for (int nf = 0; nf < 8; nf++) {
        const int cc = gn + nf * 8 + 2 * qc;
        const float2 bb = *reinterpret_cast<const float2*>(bias + cc);
#pragma unroll
        for (int mf = 0; mf < 4; mf++) {
            const int r = gm + mf * 16 + qr;
            float2 lo, hi;
            if (MODE == 1) {
                lo.x = to_tf32((acc[mf][nf][0] + bb.x) * scale);
                lo.y = to_tf32((acc[mf][nf][1] + bb.y) * scale);
                hi.x = to_tf32((acc[mf][nf][2] + bb.x) * scale);
                hi.y = to_tf32((acc[mf][nf][3] + bb.y) * scale);
            } else {
                lo.x = acc[mf][nf][0] + bb.x;
                lo.y = acc[mf][nf][1] + bb.y;
                hi.x = acc[mf][nf][2] + bb.x;
                hi.y = acc[mf][nf][3] + bb.y;
            }
            *reinterpret_cast<float2*>(Y + (size_t)r * D_ + cc) = lo;
            *reinterpret_cast<float2*>(Y + (size_t)(r + 8) * D_ + cc) = hi;
        }
    }
#undef FILLG
}

__global__ __launch_bounds__(256, 1) void qkv_gemm_kernel(
    const float* __restrict__ qi, const float* __restrict__ ki,
    const float* __restrict__ vi,
    const float* __restrict__ wq, const float* __restrict__ wk,
    const float* __restrict__ wv,
    const float* __restrict__ bq, const float* __restrict__ bk,
    const float* __restrict__ bv,
    float* __restrict__ oq, float* __restrict__ ok, float* __restrict__ ov)
{
    extern __shared__ float sm[];
    const int z = blockIdx.z;
    const float* X  = (z == 0) ? qi : (z == 1) ? ki : vi;
    const float* W  = (z == 0) ? wq : (z == 1) ? wk : wv;
    const float* bs = (z == 0) ? bq : (z == 1) ? bk : bv;
    float*       Y  = (z == 0) ? oq : (z == 1) ? ok : ov;
    const float  sc = (z == 0) ? QSCALE : 1.0f;
    gemm_body<1>(X, W, bs, Y, sc, blockIdx.x, blockIdx.y, sm);
}

__global__ __launch_bounds__(256, 1) void o_gemm_kernel(
    const float* __restrict__ X, const float* __restrict__ W,
    const float* __restrict__ bias, float* __restrict__ Y)
{
    extern __shared__ float sm[];
    gemm_body<0>(X, W, bias, Y, 1.0f, blockIdx.x, blockIdx.y, sm);
}

// ===========================================================================
// Flash attention, warp-M=32: 8 warps x 32 Q rows = 256 rows/CTA.
// Each K/V fragment feeds 2 A-fragment sets -> ~1.5x less crossbar per MMA.
// Q fragments reloaded from smem per ks (keeps regs low); P has own region.
// Smem: Qs[256][68] | Pws[8][32][68] | K0/K1[64][68] | V0/V1[64][72]
//   = 52736 words = 210944 B (1 CTA/SM).
// ===========================================================================
#define LDK 68
#define LDV 72
#define LDP 68
#define QS_OFF 0
#define PW_OFF (256 * LDP)                 // 17408
#define K0_OFF (PW_OFF + 256 * LDP)        // 34816
#define K1_OFF (K0_OFF + 64 * LDK)         // 39168
#define V0_OFF (K1_OFF + 64 * LDK)         // 43520
#define V1_OFF (V0_OFF + 64 * LDV)         // 48128
#define FLASH2_SMEM_W (V1_OFF + 64 * LDV)  // 52736
#define FLASH2_SMEM_BYTES (FLASH2_SMEM_W * 4)
#define NT (L_ / 64)                       // 32 KV tiles

__global__ __launch_bounds__(256, 1) void flash_mma_kernel(
    const float* __restrict__ Q, const float* __restrict__ K,
    const float* __restrict__ V, float* __restrict__ O)
{
    extern __shared__ float sm[];
    float* Qs = sm + QS_OFF;

    const int tid  = threadIdx.x;
    const int lane = tid & 31;
    const int w    = tid >> 5;
    const int qr   = lane >> 2;
    const int qc   = lane & 3;
    const int w32  = w * 32;

    const int q0 = blockIdx.x * 256;
    const int h  = blockIdx.y;
    const int b  = blockIdx.z;

    const float* Qg = Q + (size_t)(b * L_ + q0) * D_ + h * HD_;
    const float* Kg = K + (size_t)(b * L_) * D_ + h * HD_;
    const float* Vg = V + (size_t)(b * L_) * D_ + h * HD_;

    const uint32_t smem_base = smem_u32(sm);

    // ---- Stage Q tile [256][64] (pre-scaled tf32) into Qs
    for (int j = 0; j < 16; j++) {
        const int idx = tid + j * 256;
        const int r   = idx >> 4;
        const int c4  = (idx & 15) * 4;
        *reinterpret_cast<float4*>(Qs + r * LDP + c4) =
            *reinterpret_cast<const float4*>(Qg + (size_t)r * D_ + c4);
    }

    const int fr = tid >> 4;
    const int fc = (tid & 15) * 4;
#define FILL_TILE(kt, buf)                                                    \
    do {                                                                      \
        const float* Kt_ = Kg + (size_t)(kt) * 64 * D_;                       \
        const float* Vt_ = Vg + (size_t)(kt) * 64 * D_;                       \
        const uint32_t kb_ = smem_base + (((buf) ? K1_OFF : K0_OFF)) * 4;     \
        const uint32_t vb_ = smem_base + (((buf) ? V1_OFF : V0_OFF)) * 4;     \
        _Pragma("unroll")                                                     \
        for (int j = 0; j < 4; j++) {                                         \
            const int r_ = fr + j * 16;                                       \
            CPASYNC16(kb_ + (uint32_t)(r_ * LDK + fc) * 4,                    \
                      Kt_ + (size_t)r_ * D_ + fc);                            \
            CPASYNC16(vb_ + (uint32_t)(r_ * LDV + fc) * 4,                    \
                      Vt_ + (size_t)r_ * D_ + fc);                            \
        }                                                                     \
    } while (0)

    FILL_TILE(0, 0); CPASYNC_COMMIT();
    FILL_TILE(1, 1); CPASYNC_COMMIT();
    __syncthreads();   // Qs visible to all (also covers first-tile cp.async order)

    float oacc[2][8][4];
#pragma unroll
    for (int s = 0; s < 2; s++)
#pragma unroll
        for (int nf = 0; nf < 8; nf++)
#pragma unroll
            for (int r = 0; r < 4; r++) oacc[s][nf][r] = 0.f;
    float mrow[2][2], lrow[2][2];
#pragma unroll
    for (int s = 0; s < 2; s++) {
        mrow[s][0] = -1e30f; mrow[s][1] = -1e30f;
        lrow[s][0] = 0.f;    lrow[s][1] = 0.f;
    }

    float* Pw = sm + PW_OFF + w32 * LDP;
    const uint32_t* Pwu = reinterpret_cast<const uint32_t*>(Pw);
    const uint32_t* Qu  = reinterpret_cast<const uint32_t*>(Qs);

    for (int kt = 0; kt < NT; kt++) {
        CPASYNC_WAIT1();
        __syncthreads();

        const uint32_t* Ksu = reinterpret_cast<const uint32_t*>(
            sm + ((kt & 1) ? K1_OFF : K0_OFF));
        const uint32_t* Vsu = reinterpret_cast<const uint32_t*>(
            sm + ((kt & 1) ? V1_OFF : V0_OFF));

        // ---- S = Qs @ K^T  (32 x 64 per warp)
        float sacc[2][8][4];
#pragma unroll
        for (int s = 0; s < 2; s++)
#pragma unroll
            for (int nf = 0; nf < 8; nf++)
#pragma unroll
                for (int r = 0; r < 4; r++) sacc[s][nf][r] = 0.f;

#pragma unroll
        for (int ks = 0; ks < 8; ks++) {
            const int kb = ks * 8;
            uint32_t qa0[4], qa1[4];
            qa0[0] = Qu[(w32 + qr) * LDP + kb + qc];
            qa0[1] = Qu[(w32 + qr + 8) * LDP + kb + qc];
            qa0[2] = Qu[(w32 + qr) * LDP + kb + 4 + qc];
            qa0[3] = Qu[(w32 + qr + 8) * LDP + kb + 4 + qc];
            qa1[0] = Qu[(w32 + 16 + qr) * LDP + kb + qc];
            qa1[1] = Qu[(w32 + 24 + qr) * LDP + kb + qc];
            qa1[2] = Qu[(w32 + 16 + qr) * LDP + kb + 4 + qc];
            qa1[3] = Qu[(w32 + 24 + qr) * LDP + kb + 4 + qc];
#pragma unroll
            for (int nf = 0; nf < 8; nf++) {
                uint32_t bfr[2];
                bfr[0] = Ksu[(nf * 8 + qr) * LDK + kb + qc];
                bfr[1] = Ksu[(nf * 8 + qr) * LDK + kb + 4 + qc];
                mma_tf32_16x8x8(sacc[0][nf], qa0, bfr);
                mma_tf32_16x8x8(sacc[1][nf], qa1, bfr);
            }
        }

        // ---- Online softmax per set (rows qr, qr+8 of each 16-row set)
#pragma unroll
        for (int s = 0; s < 2; s++) {
            float mx0 = -1e30f, mx1 = -1e30f;
#pragma unroll
            for (int nf = 0; nf < 8; nf++) {
                mx0 = fmaxf(mx0, fmaxf(sacc[s][nf][0], sacc[s][nf][1]));
                mx1 = fmaxf(mx1, fmaxf(sacc[s][nf][2], sacc[s][nf][3]));
            }
            mx0 = fmaxf(mx0, __shfl_xor_sync(0xffffffffu, mx0, 1));
            mx0 = fmaxf(mx0, __shfl_xor_sync(0xffffffffu, mx0, 2));
            mx1 = fmaxf(mx1, __shfl_xor_sync(0xffffffffu, mx1, 1));
            mx1 = fmaxf(mx1, __shfl_xor_sync(0xffffffffu, mx1, 2));

            const float mn0 = fmaxf(mrow[s][0], mx0);
            const float mn1 = fmaxf(mrow[s][1], mx1);
            const float a0 = ex2_(mrow[s][0] - mn0);
            const float a1 = ex2_(mrow[s][1] - mn1);
            mrow[s][0] = mn0; mrow[s][1] = mn1;

            float s0 = 0.f, s1 = 0.f;
#pragma unroll
            for (int nf = 0; nf < 8; nf++) {
                float p0 = ex2_(sacc[s][nf][0] - mn0);
                float p1 = ex2_(sacc[s][nf][1] - mn0);
                float p2 = ex2_(sacc[s][nf][2] - mn1);
                float p3 = ex2_(sacc[s][nf][3] - mn1);
                s0 += p0 + p1; s1 += p2 + p3;
                sacc[s][nf][0] = to_tf32(p0); sacc[s][nf][1] = to_tf32(p1);
                sacc[s][nf][2] = to_tf32(p2); sacc[s][nf][3] = to_tf32(p3);
            }
            s0 += __shfl_xor_sync(0xffffffffu, s0, 1);
            s0 += __shfl_xor_sync(0xffffffffu, s0, 2);
            s1 += __shfl_xor_sync(0xffffffffu, s1, 1);
            s1 += __shfl_xor_sync(0xffffffffu, s1, 2);
            lrow[s][0] = lrow[s][0] * a0 + s0;
            lrow[s][1] = lrow[s][1] * a1 + s1;
#pragma unroll
            for (int nf = 0; nf < 8; nf++) {
                oacc[s][nf][0] *= a0; oacc[s][nf][1] *= a0;
                oacc[s][nf][2] *= a1; oacc[s][nf][3] *= a1;
            }
        }

        // ---- Store P (C-layout -> A-layout round trip), 32 rows per warp
#pragma unroll
        for (int s = 0; s < 2; s++) {
            const int rb = s * 16;
#pragma unroll
            for (int nf = 0; nf < 8; nf++) {
                float2 lo, hi;
                lo.x = sacc[s][nf][0]; lo.y = sacc[s][nf][1];
                hi.x = sacc[s][nf][2]; hi.y = sacc[s][nf][3];
                *reinterpret_cast<float2*>(Pw + (rb + qr) * LDP + nf * 8 + 2 * qc) = lo;
                *reinterpret_cast<float2*>(Pw + (rb + qr + 8) * LDP + nf * 8 + 2 * qc) = hi;
            }
        }
        __syncwarp();

        // ---- O += P @ V
#pragma unroll
        for (int ks = 0; ks < 8; ks++) {
            const int kb = ks * 8;
            uint32_t pa0[4], pa1[4];
            pa0[0] = Pwu[qr * LDP + kb + qc];
            pa0[1] = Pwu[(qr + 8) * LDP + kb + qc];
            pa0[2] = Pwu[qr * LDP + kb + 4 + qc];
            pa0[3] = Pwu[(qr + 8) * LDP + kb + 4 + qc];
            pa1[0] = Pwu[(16 + qr) * LDP + kb + qc];
            pa1[1] = Pwu[(24 + qr) * LDP + kb + qc];
            pa1[2] = Pwu[(16 + qr) * LDP + kb + 4 + qc];
            pa1[3] = Pwu[(24 + qr) * LDP + kb + 4 + qc];
#pragma unroll
            for (int nf = 0; nf < 8; nf++) {
                uint32_t vfr[2];
                vfr[0] = Vsu[(kb + qc) * LDV + nf * 8 + qr];
                vfr[1] = Vsu[(kb + 4 + qc) * LDV + nf * 8 + qr];
                mma_tf32_16x8x8(oacc[0][nf], pa0, vfr);
                mma_tf32_16x8x8(oacc[1][nf], pa1, vfr);
            }
        }

        __syncthreads();
        if (kt + 2 < NT) FILL_TILE(kt + 2, (kt & 1));
        CPASYNC_COMMIT();
    }

    // ---- Epilogue (tf32-rounded so o_gemm consumes raw bytes)
#pragma unroll
    for (int s = 0; s < 2; s++) {
        const float inv0 = 1.f / lrow[s][0];
        const float inv1 = 1.f / lrow[s][1];
        const size_t r0 = (size_t)(b * L_ + q0 + w32 + s * 16 + qr) * D_ + h * HD_;
        const size_t r1 = r0 + 8 * D_;
#pragma unroll
        for (int nf = 0; nf < 8; nf++) {
            const int cc = nf * 8 + 2 * qc;
            float2 lo, hi;
            lo.x = to_tf32(oacc[s][nf][0] * inv0);
            lo.y = to_tf32(oacc[s][nf][1] * inv0);
            hi.x = to_tf32(oacc[s][nf][2] * inv1);
            hi.y = to_tf32(oacc[s][nf][3] * inv1);
            *reinterpret_cast<float2*>(O + r0 + cc) = lo;
            *reinterpret_cast<float2*>(O + r1 + cc) = hi;
        }
    }
#undef FILL_TILE
}

// ---------------------------------------------------------------------------
// Launch
// ---------------------------------------------------------------------------
extern "C" void kernel_launch(void* const* d_in, const int* in_sizes, int n_in,
                              void* d_out, int out_size)
{
    const float* query = (const float*)d_in[0];
    const float* key   = (const float*)d_in[1];
    const float* value = (const float*)d_in[2];
    const float* Wq    = (const float*)d_in[3];
    const float* bq    = (const float*)d_in[4];
    const float* Wk    = (const float*)d_in[5];
    const float* bk    = (const float*)d_in[6];
    const float* Wv    = (const float*)d_in[7];
    const float* bv    = (const float*)d_in[8];
    const float* Wo    = (const float*)d_in[9];
    const float* bo    = (const float*)d_in[10];
    float* out = (float*)d_out;

    float *gq, *gk, *gv, *gx, *gqi, *gki, *gvi, *gwq, *gwk, *gwv, *gwo;
    cudaGetSymbolAddress((void**)&gq,  g_Q);
    cudaGetSymbolAddress((void**)&gk,  g_K);
    cudaGetSymbolAddress((void**)&gv,  g_V);
    cudaGetSymbolAddress((void**)&gx,  g_X);
    cudaGetSymbolAddress((void**)&gqi, g_QI);
    cudaGetSymbolAddress((void**)&gki, g_KI);
    cudaGetSymbolAddress((void**)&gvi, g_VI);
    cudaGetSymbolAddress((void**)&gwq, g_Wq);
    cudaGetSymbolAddress((void**)&gwk, g_Wk);
    cudaGetSymbolAddress((void**)&gwv, g_Wv);
    cudaGetSymbolAddress((void**)&gwo, g_Wo);

    cudaFuncSetAttribute(qkv_gemm_kernel,
                         cudaFuncAttributeMaxDynamicSharedMemorySize,
                         GEMM_SMEM_BYTES);
    cudaFuncSetAttribute(o_gemm_kernel,
                         cudaFuncAttributeMaxDynamicSharedMemorySize,
                         GEMM_SMEM_BYTES);
    cudaFuncSetAttribute(flash_mma_kernel,
                         cudaFuncAttributeMaxDynamicSharedMemorySize,
                         FLASH2_SMEM_BYTES);

    preround_kernel<<<dim3(MTOT * D_ / 1024, 7), 256>>>(
        query, key, value, Wq, Wk, Wv, Wo);

    qkv_gemm_kernel<<<dim3(D_ / 256, MTOT / 128, 3), 256, GEMM_SMEM_BYTES>>>(
        gqi, gki, gvi, gwq, gwk, gwv, bq, bk, bv, gq, gk, gv);

    flash_mma_kernel<<<dim3(L_ / 256, H_, B_), 256, FLASH2_SMEM_BYTES>>>(
        gq, gk, gv, gx);

    o_gemm_kernel<<<dim3(D_ / 256, MTOT / 128), 256, GEMM_SMEM_BYTES>>>(
        gx, gwo, bo, out);
}